// round 1
// baseline (speedup 1.0000x reference)
#include <cuda_runtime.h>
#include <cuda_bf16.h>

// Problem constants
#define NN 100000
#define EE 400000
#define RR 4
#define DIN 128
#define DH  128
#define NC  16
#define NCHUNK 98   // ceil(NN/1024)

// ---------------- scratch (static device globals; no allocation) ----------------
__device__ int   g_deg_in [RR*NN];
__device__ int   g_deg_out[RR*NN];
__device__ int   g_fill   [RR*NN];
__device__ int   g_rowptr [RR*(NN+1)];
__device__ int   g_partial[RR*128];
__device__ int   g_csr    [RR*EE];
__device__ float g_dsin   [RR*NN];
__device__ float g_dsout  [RR*NN];
__device__ float g_y      [NN*512];     // GEMM output, [N, R*Dout] (Dout=128 or 16)
__device__ float g_h1     [NN*128];
__device__ float g_h2     [NN*128];

// ---------------- graph preprocessing ----------------
__global__ void zero_counts_kernel() {
    int i = blockIdx.x * blockDim.x + threadIdx.x;
    if (i < RR*NN) { g_deg_in[i] = 0; g_deg_out[i] = 0; g_fill[i] = 0; }
}

__global__ void count_deg_kernel(const int* __restrict__ src, const int* __restrict__ dst) {
    int idx = blockIdx.x * blockDim.x + threadIdx.x;
    if (idx >= RR*EE) return;
    int r = idx / EE;
    atomicAdd(&g_deg_out[r*NN + src[idx]], 1);
    atomicAdd(&g_deg_in [r*NN + dst[idx]], 1);
}

// exclusive scan of g_deg_in per relation -> g_rowptr (3-phase hierarchical)
__global__ void scan1_kernel() {
    __shared__ int sh[1024];
    int r = blockIdx.y, c = blockIdx.x;
    int i = c*1024 + threadIdx.x;
    int v = (i < NN) ? g_deg_in[r*NN + i] : 0;
    sh[threadIdx.x] = v;
    __syncthreads();
    for (int off = 1; off < 1024; off <<= 1) {
        int t = (threadIdx.x >= off) ? sh[threadIdx.x - off] : 0;
        __syncthreads();
        sh[threadIdx.x] += t;
        __syncthreads();
    }
    if (i < NN) g_rowptr[r*(NN+1) + i] = sh[threadIdx.x] - v;   // exclusive within chunk
    if (threadIdx.x == 1023) g_partial[r*128 + c] = sh[1023];
}

__global__ void scan2_kernel() {
    int r = threadIdx.x;
    if (r >= RR) return;
    int run = 0;
    for (int c = 0; c < NCHUNK; c++) {
        int t = g_partial[r*128 + c];
        g_partial[r*128 + c] = run;
        run += t;
    }
    g_rowptr[r*(NN+1) + NN] = EE;
}

__global__ void scan3_kernel() {
    int r = blockIdx.y, c = blockIdx.x;
    int i = c*1024 + threadIdx.x;
    if (i < NN) g_rowptr[r*(NN+1) + i] += g_partial[r*128 + c];
}

__global__ void fill_csr_kernel(const int* __restrict__ src, const int* __restrict__ dst) {
    int idx = blockIdx.x * blockDim.x + threadIdx.x;
    if (idx >= RR*EE) return;
    int r = idx / EE;
    int d = dst[idx];
    int pos = atomicAdd(&g_fill[r*NN + d], 1);
    g_csr[r*EE + g_rowptr[r*(NN+1) + d] + pos] = src[idx];
}

__global__ void scales_kernel() {
    int i = blockIdx.x * blockDim.x + threadIdx.x;
    if (i >= RR*NN) return;
    g_dsin [i] = rsqrtf((float)max(g_deg_in [i], 1));
    g_dsout[i] = rsqrtf((float)max(g_deg_out[i], 1));
}

// ---------------- GEMM: Y[N, R*DOUT] = A[N,128] @ Wcat ----------------
// W layout is [R, 128, DOUT]; logical column c = r*DOUT + j.
template<int DOUT>
__global__ __launch_bounds__(256) void gemm_kernel(const float* __restrict__ Aext, int a_sel,
                                                   const float* __restrict__ W) {
    constexpr int BM = 128, BK = 8;
    constexpr int NTOT = RR * DOUT;
    constexpr int BN = (NTOT < 128) ? NTOT : 128;
    constexpr int TM = 8, TN = BN / 16;      // 256 threads => (128/8)*(BN/TN)=256

    const float* A = (a_sel == 0) ? Aext : ((a_sel == 1) ? g_h1 : g_h2);

    __shared__ float As[BK][BM];
    __shared__ float Ws[BK][BN];

    int tid = threadIdx.x;
    int tx = tid & 15, ty = tid >> 4;
    int blockRow = blockIdx.x * BM;
    int colBase  = blockIdx.y * BN;

    float acc[TM][TN];
    #pragma unroll
    for (int i = 0; i < TM; i++)
        #pragma unroll
        for (int j = 0; j < TN; j++) acc[i][j] = 0.0f;

    int arow = tid >> 1;
    int acol = (tid & 1) * 4;

    for (int kt = 0; kt < 128; kt += BK) {
        // load A tile (transposed into As)
        float4 av = make_float4(0.f, 0.f, 0.f, 0.f);
        int gr = blockRow + arow;
        if (gr < NN) av = *reinterpret_cast<const float4*>(&A[gr*128 + kt + acol]);
        As[acol+0][arow] = av.x;
        As[acol+1][arow] = av.y;
        As[acol+2][arow] = av.z;
        As[acol+3][arow] = av.w;
        // load W tile
        constexpr int WPR = BN / 4;
        if (tid < BK * WPR) {
            int wr = tid / WPR;
            int wc = (tid % WPR) * 4;
            int gc = colBase + wc;
            int r  = gc / DOUT;
            int j  = gc % DOUT;
            *reinterpret_cast<float4*>(&Ws[wr][wc]) =
                *reinterpret_cast<const float4*>(&W[r*128*DOUT + (kt + wr)*DOUT + j]);
        }
        __syncthreads();

        #pragma unroll
        for (int kk = 0; kk < BK; kk++) {
            float a[TM], b[TN];
            *reinterpret_cast<float4*>(&a[0]) = *reinterpret_cast<float4*>(&As[kk][ty*TM]);
            *reinterpret_cast<float4*>(&a[4]) = *reinterpret_cast<float4*>(&As[kk][ty*TM + 4]);
            #pragma unroll
            for (int j4 = 0; j4 < TN; j4 += 4)
                *reinterpret_cast<float4*>(&b[j4]) = *reinterpret_cast<float4*>(&Ws[kk][tx*TN + j4]);
            #pragma unroll
            for (int i = 0; i < TM; i++)
                #pragma unroll
                for (int j = 0; j < TN; j++)
                    acc[i][j] = fmaf(a[i], b[j], acc[i][j]);
        }
        __syncthreads();
    }

    #pragma unroll
    for (int i = 0; i < TM; i++) {
        int gr = blockRow + ty*TM + i;
        if (gr < NN) {
            #pragma unroll
            for (int j4 = 0; j4 < TN; j4 += 4) {
                float4 v = make_float4(acc[i][j4+0], acc[i][j4+1], acc[i][j4+2], acc[i][j4+3]);
                *reinterpret_cast<float4*>(&g_y[gr*NTOT + colBase + tx*TN + j4]) = v;
            }
        }
    }
}

// ---------------- CSR aggregation + scale + bias + relu + relation-mean ----------------
// out[n,j] = (1/R) * sum_r act( ds_in_r[n] * sum_{e in in(n,r)} y[src_e, r*DOUT+j]*ds_out_r[src_e] + b[r,j] )
template<int DOUT, bool RELU>
__global__ __launch_bounds__(256) void aggregate_kernel(const float* __restrict__ bias,
                                                        float* __restrict__ out_ext, int out_sel) {
    constexpr int TPN  = DOUT / 4;       // threads per node (float4 each)
    constexpr int NTOT = RR * DOUT;
    int gt   = blockIdx.x * blockDim.x + threadIdx.x;
    int node = gt / TPN;
    int lane = gt % TPN;
    if (node >= NN) return;
    float* out = (out_sel == 0) ? g_h1 : ((out_sel == 1) ? g_h2 : out_ext);

    float4 sum = make_float4(0.f, 0.f, 0.f, 0.f);
    #pragma unroll
    for (int r = 0; r < RR; r++) {
        int beg = g_rowptr[r*(NN+1) + node];
        int end = g_rowptr[r*(NN+1) + node + 1];
        float4 acc = make_float4(0.f, 0.f, 0.f, 0.f);
        for (int e = beg; e < end; e++) {
            int s = g_csr[r*EE + e];
            float w = g_dsout[r*NN + s];
            float4 v = *reinterpret_cast<const float4*>(&g_y[s*NTOT + r*DOUT + lane*4]);
            acc.x = fmaf(v.x, w, acc.x);
            acc.y = fmaf(v.y, w, acc.y);
            acc.z = fmaf(v.z, w, acc.z);
            acc.w = fmaf(v.w, w, acc.w);
        }
        float si = g_dsin[r*NN + node];
        float4 bb = *reinterpret_cast<const float4*>(&bias[r*DOUT + lane*4]);
        float vx = fmaf(acc.x, si, bb.x);
        float vy = fmaf(acc.y, si, bb.y);
        float vz = fmaf(acc.z, si, bb.z);
        float vw = fmaf(acc.w, si, bb.w);
        if (RELU) {
            vx = fmaxf(vx, 0.f); vy = fmaxf(vy, 0.f);
            vz = fmaxf(vz, 0.f); vw = fmaxf(vw, 0.f);
        }
        sum.x += vx; sum.y += vy; sum.z += vz; sum.w += vw;
    }
    sum.x *= 0.25f; sum.y *= 0.25f; sum.z *= 0.25f; sum.w *= 0.25f;
    *reinterpret_cast<float4*>(&out[node*DOUT + lane*4]) = sum;
}

// ---------------- launch ----------------
extern "C" void kernel_launch(void* const* d_in, const int* in_sizes, int n_in,
                              void* d_out, int out_size) {
    const float* x  = (const float*)d_in[0];
    const float* W0 = (const float*)d_in[1];
    const float* b0 = (const float*)d_in[2];
    const float* W1 = (const float*)d_in[3];
    const float* b1 = (const float*)d_in[4];
    const float* W2 = (const float*)d_in[5];
    const float* b2 = (const float*)d_in[6];
    const int*   src = (const int*)d_in[7];
    const int*   dst = (const int*)d_in[8];
    float* out = (float*)d_out;

    // graph preprocessing (once per launch; shared by all 3 layers)
    zero_counts_kernel<<<(RR*NN + 255)/256, 256>>>();
    count_deg_kernel  <<<(RR*EE + 255)/256, 256>>>(src, dst);
    scan1_kernel      <<<dim3(NCHUNK, RR), 1024>>>();
    scan2_kernel      <<<1, RR>>>();
    scan3_kernel      <<<dim3(NCHUNK, RR), 1024>>>();
    fill_csr_kernel   <<<(RR*EE + 255)/256, 256>>>(src, dst);
    scales_kernel     <<<(RR*NN + 255)/256, 256>>>();

    const int MB = (NN + 127) / 128;  // 782

    // layer 0: x -> h1
    gemm_kernel<128>           <<<dim3(MB, 4), 256>>>(x, 0, W0);
    aggregate_kernel<128, true><<<(NN*32 + 255)/256, 256>>>(b0, nullptr, 0);
    // layer 1: h1 -> h2
    gemm_kernel<128>           <<<dim3(MB, 4), 256>>>(nullptr, 1, W1);
    aggregate_kernel<128, true><<<(NN*32 + 255)/256, 256>>>(b1, nullptr, 1);
    // layer 2: h2 -> out
    gemm_kernel<16>             <<<dim3(MB, 1), 256>>>(nullptr, 2, W2);
    aggregate_kernel<16, false><<<(NN*4 + 255)/256, 256>>>(b2, out, 2);
}